// round 16
// baseline (speedup 1.0000x reference)
#include <cuda_runtime.h>
#include <cuda_bf16.h>
#include <math.h>
#include <stdint.h>

#define BT    4096
#define TSEQ  2048
#define DMODEL 512
#define NHEAD 8
#define DHEAD 64
#define FFDIM 2048
#define NSLOTS 32768
#define KTOP  8
#define KSEL  16
#define VSIZE 32000

// ---------------- scratch (device globals; no allocation allowed) ----------------
__device__ float g_x[BT * DMODEL];
__device__ float g_qkv[(size_t)BT * 3 * DMODEL];   // also reused as fp32 q for rescore
__device__ float g_kT[BT * DMODEL];
__device__ float g_scores[(size_t)BT * NSLOTS];

__device__ __nv_bfloat16 g_act_hi[(size_t)BT * DMODEL];
__device__ __nv_bfloat16 g_act_lo[(size_t)BT * DMODEL];
__device__ __nv_bfloat16 g_ff_hi[(size_t)BT * FFDIM];
__device__ __nv_bfloat16 g_ff_lo[(size_t)BT * FFDIM];

#define WT_ELEMS 13107200
__device__ __nv_bfloat16 g_wT_hi[WT_ELEMS];
__device__ __nv_bfloat16 g_wT_lo[WT_ELEMS];
__device__ __nv_bfloat16 g_tok_hi[(size_t)VSIZE * DMODEL];
__device__ __nv_bfloat16 g_tok_lo[(size_t)VSIZE * DMODEL];
__device__ __nv_bfloat16 g_mk_hi[(size_t)NSLOTS * DMODEL];
__device__ __nv_bfloat16 g_mk_lo[(size_t)NSLOTS * DMODEL];

// ---------------- helpers ----------------
__device__ __forceinline__ float gelu_f(float x) {
    float x3 = x * x * x;
    return 0.5f * x * (1.0f + tanhf(0.7978845608028654f * (x + 0.044715f * x3)));
}
__device__ __forceinline__ uint32_t smem_u32(const void* p) {
    uint32_t a;
    asm("{ .reg .u64 t; cvta.to.shared.u64 t, %1; cvt.u32.u64 %0, t; }" : "=r"(a) : "l"(p));
    return a;
}
__device__ __forceinline__ void split_bf16(float v, ushort& h, ushort& l) {
    __nv_bfloat16 hb = __float2bfloat16_rn(v);
    __nv_bfloat16 lb = __float2bfloat16_rn(v - __bfloat162float(hb));
    h = __bfloat16_as_ushort(hb);
    l = __bfloat16_as_ushort(lb);
}

#define LDSM4(r0, r1, r2, r3, a) \
    asm volatile("ldmatrix.sync.aligned.m8n8.x4.shared.b16 {%0,%1,%2,%3}, [%4];" \
                 : "=r"(r0), "=r"(r1), "=r"(r2), "=r"(r3) : "r"(a))
#define MMA16816(d, a, b) \
    asm volatile("mma.sync.aligned.m16n8k16.row.col.f32.bf16.bf16.f32 " \
                 "{%0,%1,%2,%3}, {%4,%5,%6,%7}, {%8,%9}, {%0,%1,%2,%3};" \
                 : "+f"((d)[0]), "+f"((d)[1]), "+f"((d)[2]), "+f"((d)[3]) \
                 : "r"((a)[0]), "r"((a)[1]), "r"((a)[2]), "r"((a)[3]), \
                   "r"((b)[0]), "r"((b)[1]))
#define CP_ASYNC16(sa, gp) \
    asm volatile("cp.async.cg.shared.global [%0], [%1], 16;" :: "r"(sa), "l"(gp))
#define CP_COMMIT() asm volatile("cp.async.commit_group;" ::: "memory")
#define CP_WAIT1()  asm volatile("cp.async.wait_group 1;" ::: "memory")

// ---------------- conversion kernels (weights / tables) ----------------
__global__ void conv_rows_kernel(const float* __restrict__ in,
                                 __nv_bfloat16* __restrict__ hi,
                                 __nv_bfloat16* __restrict__ lo) {
    size_t idx = ((size_t)blockIdx.x * 256 + threadIdx.x) * 4;
    float4 v = *(const float4*)(in + idx);
    float xs[4] = {v.x, v.y, v.z, v.w};
    ushort hs[4], ls[4];
#pragma unroll
    for (int j = 0; j < 4; j++) split_bf16(xs[j], hs[j], ls[j]);
    *(uint2*)((ushort*)hi + idx) = *(uint2*)hs;
    *(uint2*)((ushort*)lo + idx) = *(uint2*)ls;
}

__global__ void conv_T_b_kernel(const float* __restrict__ in,
                                __nv_bfloat16* __restrict__ hiT,
                                __nv_bfloat16* __restrict__ loT,
                                int K, int N, size_t zIn, size_t zOut) {
    __shared__ float tile[32][33];
    const int z = blockIdx.z;
    in  += (size_t)z * zIn;
    hiT += (size_t)z * zOut;
    loT += (size_t)z * zOut;
    int k0 = blockIdx.y * 32, n0 = blockIdx.x * 32;
    int tx = threadIdx.x, ty = threadIdx.y;
#pragma unroll
    for (int i = 0; i < 32; i += 8)
        tile[ty + i][tx] = in[(size_t)(k0 + ty + i) * N + n0 + tx];
    __syncthreads();
#pragma unroll
    for (int i = 0; i < 32; i += 8) {
        ushort h, l;
        split_bf16(tile[tx][ty + i], h, l);
        size_t o = (size_t)(n0 + ty + i) * K + k0 + tx;
        hiT[o] = __ushort_as_bfloat16(h); loT[o] = __ushort_as_bfloat16(l);
    }
}

__global__ void conv_T_qkv_kernel(const float* __restrict__ wq,
                                  const float* __restrict__ wk,
                                  const float* __restrict__ wv,
                                  __nv_bfloat16* __restrict__ hiT,
                                  __nv_bfloat16* __restrict__ loT) {
    __shared__ float tile[32][33];
    const size_t SQl = (size_t)DMODEL * DMODEL;
    const int z = blockIdx.z;
    const int which = z >> 2, l = z & 3;
    const float* in = (which == 0 ? wq : which == 1 ? wk : wv) + (size_t)l * SQl;
    __nv_bfloat16* ho = hiT + (size_t)l * 3 * SQl + (size_t)which * SQl;
    __nv_bfloat16* lo = loT + (size_t)l * 3 * SQl + (size_t)which * SQl;
    int k0 = blockIdx.y * 32, n0 = blockIdx.x * 32;
    int tx = threadIdx.x, ty = threadIdx.y;
#pragma unroll
    for (int i = 0; i < 32; i += 8)
        tile[ty + i][tx] = in[(size_t)(k0 + ty + i) * DMODEL + n0 + tx];
    __syncthreads();
#pragma unroll
    for (int i = 0; i < 32; i += 8) {
        ushort h, l2;
        split_bf16(tile[tx][ty + i], h, l2);
        size_t o = (size_t)(n0 + ty + i) * DMODEL + k0 + tx;
        ho[o] = __ushort_as_bfloat16(h); lo[o] = __ushort_as_bfloat16(l2);
    }
}

// ==================================================================================
// 64-wide NT tensor GEMM (block 128x64, 8 warps, warp 32x32)
// 2-stage cp.async double buffer, 3 CTAs/SM. TERMS: 1 = Ahi*Bhi, 2 = +Ahi*Blo,
// 3 = +Alo*Bhi. OUTHL writes bf16 hi/lo (and fp32 too when C != nullptr).
// ==================================================================================
#define ASTR 40
#define OFF_AL 5120
#define OFF_BH 10240
#define OFF_BL 12800
#define STG_B  30720
#define DSM_GEMM (2 * STG_B)    // 61440 bytes -> 3 CTAs/SM

template<int TERMS, bool BIAS, bool RES, bool GELU_ACT, bool OUTHL>
__global__ void __launch_bounds__(256, 3)
tmma_nt_kernel(const __nv_bfloat16* __restrict__ Ahi_, const __nv_bfloat16* __restrict__ Alo_,
               const __nv_bfloat16* __restrict__ Bhi_, const __nv_bfloat16* __restrict__ Blo_,
               const float* __restrict__ bias, const float* __restrict__ res,
               float* __restrict__ C,
               __nv_bfloat16* __restrict__ Chi, __nv_bfloat16* __restrict__ Clo,
               int Nout, int K, float alpha) {
    extern __shared__ __align__(16) ushort dsm[];
    const uint32_t base = smem_u32(dsm);

    const int tid = threadIdx.x;
    const int wid = tid >> 5, lane = tid & 31;
    const int bm = blockIdx.y * 128, bn = blockIdx.x * 64;
    const int wm = wid & 3, wn = wid >> 2;
    const int g = lane >> 2, t = lane & 3;
    const int lq = lane >> 3, lr = lane & 7;

    float acc[2][4][4];
#pragma unroll
    for (int i = 0; i < 2; i++)
#pragma unroll
        for (int j = 0; j < 4; j++)
#pragma unroll
            for (int c = 0; c < 4; c++) acc[i][j][c] = 0.f;

    const int arow = tid >> 1, aseg = tid & 1;
    const int brow = tid >> 2, bseg = tid & 3;
    const ushort* gAh = (const ushort*)Ahi_ + (size_t)(bm + arow) * K + aseg * 16;
    const ushort* gAl = (const ushort*)Alo_ + (size_t)(bm + arow) * K + aseg * 16;
    const ushort* gBh = (const ushort*)Bhi_ + (size_t)(bn + brow) * K + bseg * 8;
    const ushort* gBl = (const ushort*)Blo_ + (size_t)(bn + brow) * K + bseg * 8;
    const uint32_t dA = (uint32_t)((arow * ASTR + aseg * 16) * 2);
    const uint32_t dB = (uint32_t)((brow * ASTR + bseg * 8) * 2);

#define TISSUE(sb, kc) do { \
        CP_ASYNC16((sb) + dA, gAh + (kc)); \
        CP_ASYNC16((sb) + dA + 16, gAh + (kc) + 8); \
        if (TERMS == 3) { \
            CP_ASYNC16((sb) + OFF_AL * 2 + dA, gAl + (kc)); \
            CP_ASYNC16((sb) + OFF_AL * 2 + dA + 16, gAl + (kc) + 8); \
        } \
        CP_ASYNC16((sb) + OFF_BH * 2 + dB, gBh + (kc)); \
        if (TERMS >= 2) CP_ASYNC16((sb) + OFF_BL * 2 + dB, gBl + (kc)); \
    } while (0)

    uint32_t aoff[2], boff[2];
#pragma unroll
    for (int mt = 0; mt < 2; mt++) {
        int row = wm * 32 + mt * 16 + (lq & 1) * 8 + lr;
        int col = (lq >> 1) * 8;
        aoff[mt] = (uint32_t)((row * ASTR + col) * 2);
    }
#pragma unroll
    for (int p = 0; p < 2; p++) {
        int row = wn * 32 + p * 16 + (lq >> 1) * 8 + lr;
        int col = (lq & 1) * 8;
        boff[p] = (uint32_t)((row * ASTR + col) * 2);
    }

    const int nch = K >> 5;
    TISSUE(base, 0);
    CP_COMMIT();

    for (int ch = 0; ch < nch; ch++) {
        if (ch + 1 < nch) {
            TISSUE(base + ((ch + 1) & 1) * STG_B, (ch + 1) * 32);
        }
        CP_COMMIT();
        CP_WAIT1();
        __syncthreads();

        const uint32_t sb = base + (ch & 1) * STG_B;
#pragma unroll
        for (int kk = 0; kk < 32; kk += 16) {
            const uint32_t kb = (uint32_t)(kk * 2);
            uint32_t rah[2][4], ral[2][4], rbh[2][4], rbl[2][4];
#pragma unroll
            for (int mt = 0; mt < 2; mt++) {
                LDSM4(rah[mt][0], rah[mt][1], rah[mt][2], rah[mt][3], sb + aoff[mt] + kb);
                if (TERMS == 3)
                    LDSM4(ral[mt][0], ral[mt][1], ral[mt][2], ral[mt][3],
                          sb + OFF_AL * 2 + aoff[mt] + kb);
            }
#pragma unroll
            for (int p = 0; p < 2; p++) {
                LDSM4(rbh[p][0], rbh[p][1], rbh[p][2], rbh[p][3],
                      sb + OFF_BH * 2 + boff[p] + kb);
                if (TERMS >= 2)
                    LDSM4(rbl[p][0], rbl[p][1], rbl[p][2], rbl[p][3],
                          sb + OFF_BL * 2 + boff[p] + kb);
            }
#pragma unroll
            for (int mt = 0; mt < 2; mt++)
#pragma unroll
                for (int p = 0; p < 2; p++)
#pragma unroll
                    for (int sub = 0; sub < 2; sub++) {
                        const int nt = 2 * p + sub;
                        MMA16816(acc[mt][nt], rah[mt], &rbh[p][2 * sub]);
                        if (TERMS >= 2) MMA16816(acc[mt][nt], rah[mt], &rbl[p][2 * sub]);
                        if (TERMS == 3) MMA16816(acc[mt][nt], ral[mt], &rbh[p][2 * sub]);
                    }
        }
        __syncthreads();
    }
#undef TISSUE

#pragma unroll
    for (int mt = 0; mt < 2; mt++) {
        int row0 = bm + wm * 32 + mt * 16 + g;
#pragma unroll
        for (int nt = 0; nt < 4; nt++) {
            int col = bn + wn * 32 + nt * 8 + t * 2;
#pragma unroll
            for (int h = 0; h < 2; h++) {
                int r = row0 + h * 8;
                float v0 = acc[mt][nt][h * 2 + 0] * alpha;
                float v1 = acc[mt][nt][h * 2 + 1] * alpha;
                if (BIAS) {
                    const float2 bv = *(const float2*)(bias + col);
                    v0 += bv.x; v1 += bv.y;
                }
                if (RES) {
                    const float2 rr = *(const float2*)(res + (size_t)r * Nout + col);
                    v0 += rr.x; v1 += rr.y;
                }
                if (GELU_ACT) { v0 = gelu_f(v0); v1 = gelu_f(v1); }
                if (OUTHL) {
                    ushort h0, l0, h1, l1;
                    split_bf16(v0, h0, l0);
                    split_bf16(v1, h1, l1);
                    *(uint32_t*)((ushort*)Chi + (size_t)r * Nout + col) =
                        ((uint32_t)h1 << 16) | h0;
                    *(uint32_t*)((ushort*)Clo + (size_t)r * Nout + col) =
                        ((uint32_t)l1 << 16) | l0;
                    if (C) *(float2*)(C + (size_t)r * Nout + col) = make_float2(v0, v1);
                } else {
                    *(float2*)(C + (size_t)r * Nout + col) = make_float2(v0, v1);
                }
            }
        }
    }
}

// ---------------- embedding (+ hi/lo) ----------------
__global__ void embed_conv_kernel(const int* __restrict__ ids,
                                  const float* __restrict__ tok,
                                  const float* __restrict__ pos,
                                  float* __restrict__ x,
                                  __nv_bfloat16* __restrict__ hi,
                                  __nv_bfloat16* __restrict__ lo) {
    int t = blockIdx.x;
    int s = t & (TSEQ - 1);
    int id = ids[t];
    const float* tp = tok + (size_t)id * DMODEL;
    const float* pp = pos + (size_t)s * DMODEL;
    size_t o = (size_t)t * DMODEL;
    for (int d = threadIdx.x; d < DMODEL; d += 256) {
        float v = tp[d] + pp[d];
        x[o + d] = v;
        ushort h, l;
        split_bf16(v, h, l);
        hi[o + d] = __ushort_as_bfloat16(h);
        lo[o + d] = __ushort_as_bfloat16(l);
    }
}

// ---------------- RMS norm (+ hi/lo) ----------------
__global__ void rms_conv_kernel(float* __restrict__ x, const float* __restrict__ w,
                                __nv_bfloat16* __restrict__ hi,
                                __nv_bfloat16* __restrict__ lo) {
    __shared__ float sred[256];
    int t = blockIdx.x;
    int tid = threadIdx.x;
    float* row = x + (size_t)t * DMODEL;
    float v0 = row[tid];
    float v1 = row[tid + 256];
    sred[tid] = v0 * v0 + v1 * v1;
    __syncthreads();
    for (int s = 128; s > 0; s >>= 1) {
        if (tid < s) sred[tid] += sred[tid + s];
        __syncthreads();
    }
    float r = rsqrtf(sred[0] / (float)DMODEL + 1e-8f);
    float o0 = v0 * r * w[tid];
    float o1 = v1 * r * w[tid + 256];
    row[tid] = o0; row[tid + 256] = o1;
    size_t o = (size_t)t * DMODEL;
    ushort h, l;
    split_bf16(o0, h, l);
    hi[o + tid] = __ushort_as_bfloat16(h); lo[o + tid] = __ushort_as_bfloat16(l);
    split_bf16(o1, h, l);
    hi[o + tid + 256] = __ushort_as_bfloat16(h); lo[o + tid + 256] = __ushort_as_bfloat16(l);
}

// ---------------- K transpose ----------------
__global__ void transpose_k_kernel(const float* __restrict__ QKV, float* __restrict__ KT) {
    __shared__ float tile[32][33];
    int b = blockIdx.z;
    int t0 = blockIdx.y * 32;
    int c0 = blockIdx.x * 32;
    int tx = threadIdx.x, ty = threadIdx.y;
#pragma unroll
    for (int i = 0; i < 32; i += 8)
        tile[ty + i][tx] = QKV[(size_t)(b * TSEQ + t0 + ty + i) * (3 * DMODEL) + DMODEL + c0 + tx];
    __syncthreads();
#pragma unroll
    for (int i = 0; i < 32; i += 8)
        KT[(size_t)(b * DMODEL + c0 + ty + i) * TSEQ + t0 + tx] = tile[tx][ty + i];
}

// ---------------- attention ----------------
#define ATT_Q 16
#define ATT_T 512
#define ATT_SMEM ((ATT_Q * TSEQ + DHEAD * ATT_Q + 8 * ATT_Q * DHEAD + ATT_Q) * 4)

__global__ void attn_kernel(const float* __restrict__ QKV, const float* __restrict__ KT,
                            __nv_bfloat16* __restrict__ Ohi, __nv_bfloat16* __restrict__ Olo) {
    extern __shared__ float smem[];
    float* sS    = smem;
    float* sQT   = sS + ATT_Q * TSEQ;
    float* sPart = sQT + DHEAD * ATT_Q;
    float* sL    = sPart + 8 * ATT_Q * DHEAD;
    const int b = blockIdx.z, h = blockIdx.y;
    const int q0 = blockIdx.x * ATT_Q;
    const int tid = threadIdx.x;

    for (int i = tid; i < ATT_Q * DHEAD; i += ATT_T) {
        int qi = i >> 6, d = i & 63;
        sQT[d * ATT_Q + qi] =
            QKV[(size_t)(b * TSEQ + q0 + qi) * (3 * DMODEL) + h * DHEAD + d];
    }
    __syncthreads();

    {
        const float* kbase = KT + ((size_t)(b * DMODEL) + h * DHEAD) * TSEQ;
        for (int k = tid; k < TSEQ; k += ATT_T) {
            float a[ATT_Q];
#pragma unroll
            for (int qi = 0; qi < ATT_Q; qi++) a[qi] = 0.f;
#pragma unroll 8
            for (int d = 0; d < DHEAD; d++) {
                float kv = kbase[(size_t)d * TSEQ + k];
                const float4* qp = (const float4*)(sQT + d * ATT_Q);
                float4 q0v = qp[0], q1v = qp[1], q2v = qp[2], q3v = qp[3];
                a[0]  += kv * q0v.x; a[1]  += kv * q0v.y; a[2]  += kv * q0v.z; a[3]  += kv * q0v.w;
                a[4]  += kv * q1v.x; a[5]  += kv * q1v.y; a[6]  += kv * q1v.z; a[7]  += kv * q1v.w;
                a[8]  += kv * q2v.x; a[9]  += kv * q2v.y; a[10] += kv * q2v.z; a[11] += kv * q2v.w;
                a[12] += kv * q3v.x; a[13] += kv * q3v.y; a[14] += kv * q3v.z; a[15] += kv * q3v.w;
            }
#pragma unroll
            for (int qi = 0; qi < ATT_Q; qi++) sS[qi * TSEQ + k] = a[qi] * 0.125f;
        }
    }
    __syncthreads();

    {
        const int w = tid >> 5, lane = tid & 31;
        float* row = sS + w * TSEQ;
        float m = -INFINITY;
        for (int k = lane; k < TSEQ; k += 32) m = fmaxf(m, row[k]);
#pragma unroll
        for (int o = 16; o > 0; o >>= 1) m = fmaxf(m, __shfl_xor_sync(0xFFFFFFFF, m, o));
        float sum = 0.f;
        for (int k = lane; k < TSEQ; k += 32) {
            float e = expf(row[k] - m);
            row[k] = e;
            sum += e;
        }
#pragma unroll
        for (int o = 16; o > 0; o >>= 1) sum += __shfl_xor_sync(0xFFFFFFFF, sum, o);
        if (lane == 0) sL[w] = sum;
    }
    __syncthreads();

    {
        int d = tid & 63, chunk = tid >> 6;
        const float* vbase = QKV + (size_t)(b * TSEQ) * (3 * DMODEL) + 2 * DMODEL + h * DHEAD + d;
        float a[ATT_Q];
#pragma unroll
        for (int qi = 0; qi < ATT_Q; qi++) a[qi] = 0.f;
        int k0 = chunk * (TSEQ / 8);
        for (int k = k0; k < k0 + TSEQ / 8; k++) {
            float vv = vbase[(size_t)k * (3 * DMODEL)];
#pragma unroll
            for (int qi = 0; qi < ATT_Q; qi++) a[qi] += sS[qi * TSEQ + k] * vv;
        }
#pragma unroll
        for (int qi = 0; qi < ATT_Q; qi++)
            sPart[(chunk * ATT_Q + qi) * DHEAD + d] = a[qi];
    }
    __syncthreads();
    for (int i = tid; i < ATT_Q * DHEAD; i += ATT_T) {
        int qi = i >> 6, d = i & 63;
        float s = 0.f;
#pragma unroll
        for (int c = 0; c < 8; c++) s += sPart[(c * ATT_Q + qi) * DHEAD + d];
        float o = s / sL[qi];
        ushort hh, ll;
        split_bf16(o, hh, ll);
        size_t oo = (size_t)(b * TSEQ + q0 + qi) * DMODEL + h * DHEAD + d;
        Ohi[oo] = __ushort_as_bfloat16(hh);
        Olo[oo] = __ushort_as_bfloat16(ll);
    }
}

// ---------------- top-16 select + exact fp32 rescore -> top-8 + gather ----------------
__global__ void topk_read_kernel(const float* __restrict__ scores,
                                 const float* __restrict__ memV,
                                 const float* __restrict__ qf,      // fp32 q [BT,512]
                                 const float* __restrict__ memK,    // fp32 [NSLOTS,512]
                                 const float* __restrict__ sal,
                                 __nv_bfloat16* __restrict__ rdhi,
                                 __nv_bfloat16* __restrict__ rdlo) {
    __shared__ float ssc[256][KSEL];
    __shared__ int   sid[256][KSEL];
    __shared__ int   scand[KSEL];
    __shared__ float sexact[KSEL];
    __shared__ float sw[KTOP];
    __shared__ int   swi[KTOP];
    const int t = blockIdx.x;
    const int tid = threadIdx.x;
    const float* row = scores + (size_t)t * NSLOTS;

    // per-thread top-16 over the approximate scores
    float ls[KSEL]; int li[KSEL];
#pragma unroll
    for (int j = 0; j < KSEL; j++) { ls[j] = -INFINITY; li[j] = -1; }
    for (int s = tid; s < NSLOTS; s += 256) {
        float v = row[s];
        if (v > ls[KSEL - 1]) {
            int j = KSEL - 1;
            while (j > 0 && ls[j - 1] < v) { ls[j] = ls[j - 1]; li[j] = li[j - 1]; j--; }
            ls[j] = v; li[j] = s;
        }
    }
#pragma unroll
    for (int j = 0; j < KSEL; j++) { ssc[tid][j] = ls[j]; sid[tid][j] = li[j]; }

    for (int stride = 128; stride >= 1; stride >>= 1) {
        __syncthreads();
        if (tid < stride) {
            float oa[KSEL]; int oi[KSEL];
            int ai = 0, bi = 0;
#pragma unroll
            for (int j = 0; j < KSEL; j++) {
                float av = ssc[tid][ai], bv = ssc[tid + stride][bi];
                if (av >= bv) { oa[j] = av; oi[j] = sid[tid][ai]; ai++; }
                else          { oa[j] = bv; oi[j] = sid[tid + stride][bi]; bi++; }
            }
#pragma unroll
            for (int j = 0; j < KSEL; j++) { ssc[tid][j] = oa[j]; sid[tid][j] = oi[j]; }
        }
    }
    __syncthreads();
    if (tid < KSEL) scand[tid] = sid[0][tid];
    __syncthreads();

    // exact fp32 rescore of the 16 candidates: score = (q . memK[c]) * 1/sqrt(512) + sal[c]
    {
        const int w = tid >> 5, lane = tid & 31;
        const float* qr = qf + (size_t)t * DMODEL;
        for (int c = w; c < KSEL; c += 8) {
            const int slot = scand[c];
            const float* kr = memK + (size_t)slot * DMODEL;
            float s = 0.f;
            for (int i = lane; i < DMODEL; i += 32) s += qr[i] * kr[i];
#pragma unroll
            for (int o = 16; o > 0; o >>= 1) s += __shfl_xor_sync(0xFFFFFFFF, s, o);
            if (lane == 0)
                sexact[c] = s * 0.044194173824159216f + sal[slot];
        }
    }
    __syncthreads();

    // exact top-8 of the 16, softmax
    if (tid == 0) {
        float bs[KTOP]; int bi[KTOP];
#pragma unroll
        for (int j = 0; j < KTOP; j++) { bs[j] = -INFINITY; bi[j] = -1; }
        for (int c = 0; c < KSEL; c++) {
            float v = sexact[c];
            if (v > bs[KTOP - 1]) {
                int j = KTOP - 1;
                while (j > 0 && bs[j - 1] < v) { bs[j] = bs[j - 1]; bi[j] = bi[j - 1]; j--; }
                bs[j] = v; bi[j] = scand[c];
            }
        }
        float m = bs[0];
        float e[KTOP]; float sum = 0.f;
#pragma unroll
        for (int j = 0; j < KTOP; j++) { e[j] = expf(bs[j] - m); sum += e[j]; }
        float inv = 1.f / sum;
#pragma unroll
        for (int j = 0; j < KTOP; j++) { sw[j] = e[j] * inv; swi[j] = bi[j]; }
    }
    __syncthreads();

    for (int d = tid; d < DMODEL; d += 256) {
        float acc = 0.f;
#pragma unroll
        for (int j = 0; j < KTOP; j++)
            acc += sw[j] * memV[(size_t)swi[j] * DMODEL + d];
        ushort h, l;
        split_bf16(acc, h, l);
        size_t o = (size_t)t * DMODEL + d;
        rdhi[o] = __ushort_as_bfloat16(h);
        rdlo[o] = __ushort_as_bfloat16(l);
    }
}

// ---------------- host orchestration ----------------
extern "C" void kernel_launch(void* const* d_in, const int* in_sizes, int n_in,
                              void* d_out, int out_size) {
    const int*   ids      = (const int*)  d_in[0];
    const float* tok      = (const float*)d_in[1];
    const float* pos      = (const float*)d_in[2];
    const float* wq       = (const float*)d_in[3];
    const float* wk       = (const float*)d_in[4];
    const float* wv       = (const float*)d_in[5];
    const float* wo       = (const float*)d_in[6];
    const float* bo       = (const float*)d_in[7];
    const float* norm1    = (const float*)d_in[8];
    const float* ffw1     = (const float*)d_in[9];
    const float* ffb1     = (const float*)d_in[10];
    const float* ffw2     = (const float*)d_in[11];
    const float* ffb2     = (const float*)d_in[12];
    const float* norm2    = (const float*)d_in[13];
    const float* memK     = (const float*)d_in[14];
    const float* memV     = (const float*)d_in[15];
    const float* salience = (const float*)d_in[16];
    const float* wq_mem   = (const float*)d_in[17];
    const float* bq_mem   = (const float*)d_in[18];
    const float* w_read   = (const float*)d_in[19];
    const float* b_read   = (const float*)d_in[20];
    const float* norm_out = (const float*)d_in[21];
    float* out = (float*)d_out;

    float *x, *qkv, *kT, *sc;
    cudaGetSymbolAddress((void**)&x,   g_x);
    cudaGetSymbolAddress((void**)&qkv, g_qkv);
    cudaGetSymbolAddress((void**)&kT,  g_kT);
    cudaGetSymbolAddress((void**)&sc,  g_scores);

    __nv_bfloat16 *wThi, *wTlo, *tokhi, *toklo, *mkhi, *mklo, *acthi, *actlo, *ffh, *ffl;
    cudaGetSymbolAddress((void**)&wThi,  g_wT_hi);
    cudaGetSymbolAddress((void**)&wTlo,  g_wT_lo);
    cudaGetSymbolAddress((void**)&tokhi, g_tok_hi);
    cudaGetSymbolAddress((void**)&toklo, g_tok_lo);
    cudaGetSymbolAddress((void**)&mkhi,  g_mk_hi);
    cudaGetSymbolAddress((void**)&mklo,  g_mk_lo);
    cudaGetSymbolAddress((void**)&acthi, g_act_hi);
    cudaGetSymbolAddress((void**)&actlo, g_act_lo);
    cudaGetSymbolAddress((void**)&ffh,   g_ff_hi);
    cudaGetSymbolAddress((void**)&ffl,   g_ff_lo);

    const size_t SQ = (size_t)DMODEL * DMODEL;
    const size_t SF = (size_t)DMODEL * FFDIM;
    const size_t OFF_QKV = 0;
    const size_t OFF_O   = 12 * SQ;
    const size_t OFF_F1  = 16 * SQ;
    const size_t OFF_F2  = OFF_F1 + 4 * SF;
    const size_t OFF_QM  = OFF_F2 + 4 * SF;
    const size_t OFF_RD  = OFF_QM + SQ;

    cudaFuncSetAttribute(tmma_nt_kernel<3, false, false, false, false>, cudaFuncAttributeMaxDynamicSharedMemorySize, DSM_GEMM);
    cudaFuncSetAttribute(tmma_nt_kernel<3, true, true, false, false>,   cudaFuncAttributeMaxDynamicSharedMemorySize, DSM_GEMM);
    cudaFuncSetAttribute(tmma_nt_kernel<3, true, false, true, true>,    cudaFuncAttributeMaxDynamicSharedMemorySize, DSM_GEMM);
    cudaFuncSetAttribute(tmma_nt_kernel<3, true, false, false, true>,   cudaFuncAttributeMaxDynamicSharedMemorySize, DSM_GEMM);
    cudaFuncSetAttribute(tmma_nt_kernel<1, true, false, false, false>,  cudaFuncAttributeMaxDynamicSharedMemorySize, DSM_GEMM);
    cudaFuncSetAttribute(attn_kernel, cudaFuncAttributeMaxDynamicSharedMemorySize, ATT_SMEM);

    const dim3 ct(32, 8);
    const dim3 g512(DMODEL / 64, BT / 128);
    const dim3 gqkv(3 * DMODEL / 64, BT / 128);
    const dim3 g2048(FFDIM / 64, BT / 128);

    // launches ordered so the profiler window hits GEMM / transpose / attn
    conv_T_qkv_kernel<<<dim3(16, 16, 12), ct>>>(wq, wk, wv, wThi + OFF_QKV, wTlo + OFF_QKV);
    conv_T_b_kernel<<<dim3(16, 16, 4), ct>>>(wo, wThi + OFF_O, wTlo + OFF_O, DMODEL, DMODEL, SQ, SQ);
    embed_conv_kernel<<<BT, 256>>>(ids, tok, pos, x, acthi, actlo);
    tmma_nt_kernel<3, false, false, false, false><<<gqkv, 256, DSM_GEMM>>>(
        acthi, actlo, wThi + OFF_QKV, wTlo + OFF_QKV, nullptr, nullptr,
        qkv, nullptr, nullptr, 3 * DMODEL, DMODEL, 1.f);
    transpose_k_kernel<<<dim3(DMODEL / 32, TSEQ / 32, 2), dim3(32, 8)>>>(qkv, kT);
    attn_kernel<<<dim3(TSEQ / ATT_Q, NHEAD, 2), ATT_T, ATT_SMEM>>>(qkv, kT, acthi, actlo);

    // remaining conversions
    conv_T_b_kernel<<<dim3(FFDIM / 32, DMODEL / 32, 4), ct>>>(ffw1, wThi + OFF_F1, wTlo + OFF_F1, DMODEL, FFDIM, SF, SF);
    conv_T_b_kernel<<<dim3(DMODEL / 32, FFDIM / 32, 4), ct>>>(ffw2, wThi + OFF_F2, wTlo + OFF_F2, FFDIM, DMODEL, SF, SF);
    conv_T_b_kernel<<<dim3(16, 16, 1), ct>>>(wq_mem, wThi + OFF_QM, wTlo + OFF_QM, DMODEL, DMODEL, 0, 0);
    conv_T_b_kernel<<<dim3(16, 16, 1), ct>>>(w_read, wThi + OFF_RD, wTlo + OFF_RD, DMODEL, DMODEL, 0, 0);
    conv_rows_kernel<<<(int)((size_t)VSIZE * DMODEL / 1024), 256>>>(tok, tokhi, toklo);
    conv_rows_kernel<<<(int)((size_t)NSLOTS * DMODEL / 1024), 256>>>(memK, mkhi, mklo);

    // layer 0 remainder + layers 1..3
    for (int l = 0; l < 4; l++) {
        if (l > 0) {
            tmma_nt_kernel<3, false, false, false, false><<<gqkv, 256, DSM_GEMM>>>(
                acthi, actlo, wThi + OFF_QKV + l * 3 * SQ, wTlo + OFF_QKV + l * 3 * SQ,
                nullptr, nullptr, qkv, nullptr, nullptr, 3 * DMODEL, DMODEL, 1.f);
            transpose_k_kernel<<<dim3(DMODEL / 32, TSEQ / 32, 2), dim3(32, 8)>>>(qkv, kT);
            attn_kernel<<<dim3(TSEQ / ATT_Q, NHEAD, 2), ATT_T, ATT_SMEM>>>(qkv, kT, acthi, actlo);
        }

        tmma_nt_kernel<3, true, true, false, false><<<g512, 256, DSM_GEMM>>>(
            acthi, actlo, wThi + OFF_O + l * SQ, wTlo + OFF_O + l * SQ,
            bo + l * DMODEL, x, x, nullptr, nullptr, DMODEL, DMODEL, 1.f);
        rms_conv_kernel<<<BT, 256>>>(x, norm1 + l * DMODEL, acthi, actlo);

        tmma_nt_kernel<3, true, false, true, true><<<g2048, 256, DSM_GEMM>>>(
            acthi, actlo, wThi + OFF_F1 + l * SF, wTlo + OFF_F1 + l * SF,
            ffb1 + l * FFDIM, nullptr, nullptr, ffh, ffl, FFDIM, DMODEL, 1.f);
        tmma_nt_kernel<3, true, true, false, false><<<g512, 256, DSM_GEMM>>>(
            ffh, ffl, wThi + OFF_F2 + l * SF, wTlo + OFF_F2 + l * SF,
            ffb2 + l * DMODEL, x, x, nullptr, nullptr, DMODEL, FFDIM, 1.f);
        rms_conv_kernel<<<BT, 256>>>(x, norm2 + l * DMODEL, acthi, actlo);
    }

    // external memory read: q (hi/lo for approx scores, fp32 for exact rescore)
    tmma_nt_kernel<3, true, false, false, true><<<g512, 256, DSM_GEMM>>>(
        acthi, actlo, wThi + OFF_QM, wTlo + OFF_QM,
        bq_mem, nullptr, qkv, ffh, ffl, DMODEL, DMODEL, 1.f);
    // approx scores: single-term bf16 (selection only; rescored exactly below)
    tmma_nt_kernel<1, true, false, false, false><<<dim3(NSLOTS / 64, BT / 128), 256, DSM_GEMM>>>(
        ffh, ffl, mkhi, mklo, salience, nullptr, sc, nullptr, nullptr,
        NSLOTS, DMODEL, 0.044194173824159216f /* 512^-0.5 */);
    topk_read_kernel<<<BT, 256>>>(sc, memV, qkv, memK, salience, acthi, actlo);
    tmma_nt_kernel<3, true, true, false, false><<<g512, 256, DSM_GEMM>>>(
        acthi, actlo, wThi + OFF_RD, wTlo + OFF_RD,
        b_read, x, x, nullptr, nullptr, DMODEL, DMODEL, 1.f);
    rms_conv_kernel<<<BT, 256>>>(x, norm_out, acthi, actlo);

    // tied LM head -> d_out
    tmma_nt_kernel<3, false, false, false, false><<<dim3(VSIZE / 64, BT / 128), 256, DSM_GEMM>>>(
        acthi, actlo, tokhi, toklo, nullptr, nullptr, out, nullptr, nullptr,
        VSIZE, DMODEL, 1.f);
}

// round 17
// speedup vs baseline: 1.5338x; 1.5338x over previous
#include <cuda_runtime.h>
#include <cuda_bf16.h>
#include <math.h>
#include <stdint.h>

#define BT    4096
#define TSEQ  2048
#define DMODEL 512
#define NHEAD 8
#define DHEAD 64
#define FFDIM 2048
#define NSLOTS 32768
#define KTOP  8
#define VSIZE 32000

// ---------------- scratch (device globals; no allocation allowed) ----------------
__device__ float g_x[BT * DMODEL];
__device__ float g_qkv[(size_t)BT * 3 * DMODEL];
__device__ float g_kT[BT * DMODEL];
__device__ float g_scores[(size_t)BT * NSLOTS];

__device__ __nv_bfloat16 g_act_hi[(size_t)BT * DMODEL];
__device__ __nv_bfloat16 g_act_lo[(size_t)BT * DMODEL];
__device__ __nv_bfloat16 g_ff_hi[(size_t)BT * FFDIM];
__device__ __nv_bfloat16 g_ff_lo[(size_t)BT * FFDIM];

#define WT_ELEMS 13107200
__device__ __nv_bfloat16 g_wT_hi[WT_ELEMS];
__device__ __nv_bfloat16 g_wT_lo[WT_ELEMS];
__device__ __nv_bfloat16 g_tok_hi[(size_t)VSIZE * DMODEL];
__device__ __nv_bfloat16 g_tok_lo[(size_t)VSIZE * DMODEL];
__device__ __nv_bfloat16 g_mk_hi[(size_t)NSLOTS * DMODEL];
__device__ __nv_bfloat16 g_mk_lo[(size_t)NSLOTS * DMODEL];

// ---------------- helpers ----------------
__device__ __forceinline__ float gelu_f(float x) {
    float x3 = x * x * x;
    return 0.5f * x * (1.0f + tanhf(0.7978845608028654f * (x + 0.044715f * x3)));
}
__device__ __forceinline__ uint32_t smem_u32(const void* p) {
    uint32_t a;
    asm("{ .reg .u64 t; cvta.to.shared.u64 t, %1; cvt.u32.u64 %0, t; }" : "=r"(a) : "l"(p));
    return a;
}
__device__ __forceinline__ void split_bf16(float v, ushort& h, ushort& l) {
    __nv_bfloat16 hb = __float2bfloat16_rn(v);
    __nv_bfloat16 lb = __float2bfloat16_rn(v - __bfloat162float(hb));
    h = __bfloat16_as_ushort(hb);
    l = __bfloat16_as_ushort(lb);
}

#define LDSM4(r0, r1, r2, r3, a) \
    asm volatile("ldmatrix.sync.aligned.m8n8.x4.shared.b16 {%0,%1,%2,%3}, [%4];" \
                 : "=r"(r0), "=r"(r1), "=r"(r2), "=r"(r3) : "r"(a))
#define MMA16816(d, a, b) \
    asm volatile("mma.sync.aligned.m16n8k16.row.col.f32.bf16.bf16.f32 " \
                 "{%0,%1,%2,%3}, {%4,%5,%6,%7}, {%8,%9}, {%0,%1,%2,%3};" \
                 : "+f"((d)[0]), "+f"((d)[1]), "+f"((d)[2]), "+f"((d)[3]) \
                 : "r"((a)[0]), "r"((a)[1]), "r"((a)[2]), "r"((a)[3]), \
                   "r"((b)[0]), "r"((b)[1]))
#define CP_ASYNC16(sa, gp) \
    asm volatile("cp.async.cg.shared.global [%0], [%1], 16;" :: "r"(sa), "l"(gp))
#define CP_COMMIT() asm volatile("cp.async.commit_group;" ::: "memory")
#define CP_WAIT1()  asm volatile("cp.async.wait_group 1;" ::: "memory")

// ---------------- conversion kernels (weights / tables) ----------------
__global__ void conv_rows_kernel(const float* __restrict__ in,
                                 __nv_bfloat16* __restrict__ hi,
                                 __nv_bfloat16* __restrict__ lo) {
    size_t idx = ((size_t)blockIdx.x * 256 + threadIdx.x) * 4;
    float4 v = *(const float4*)(in + idx);
    float xs[4] = {v.x, v.y, v.z, v.w};
    ushort hs[4], ls[4];
#pragma unroll
    for (int j = 0; j < 4; j++) split_bf16(xs[j], hs[j], ls[j]);
    *(uint2*)((ushort*)hi + idx) = *(uint2*)hs;
    *(uint2*)((ushort*)lo + idx) = *(uint2*)ls;
}

__global__ void conv_T_b_kernel(const float* __restrict__ in,
                                __nv_bfloat16* __restrict__ hiT,
                                __nv_bfloat16* __restrict__ loT,
                                int K, int N, size_t zIn, size_t zOut) {
    __shared__ float tile[32][33];
    const int z = blockIdx.z;
    in  += (size_t)z * zIn;
    hiT += (size_t)z * zOut;
    loT += (size_t)z * zOut;
    int k0 = blockIdx.y * 32, n0 = blockIdx.x * 32;
    int tx = threadIdx.x, ty = threadIdx.y;
#pragma unroll
    for (int i = 0; i < 32; i += 8)
        tile[ty + i][tx] = in[(size_t)(k0 + ty + i) * N + n0 + tx];
    __syncthreads();
#pragma unroll
    for (int i = 0; i < 32; i += 8) {
        ushort h, l;
        split_bf16(tile[tx][ty + i], h, l);
        size_t o = (size_t)(n0 + ty + i) * K + k0 + tx;
        hiT[o] = __ushort_as_bfloat16(h); loT[o] = __ushort_as_bfloat16(l);
    }
}

__global__ void conv_T_qkv_kernel(const float* __restrict__ wq,
                                  const float* __restrict__ wk,
                                  const float* __restrict__ wv,
                                  __nv_bfloat16* __restrict__ hiT,
                                  __nv_bfloat16* __restrict__ loT) {
    __shared__ float tile[32][33];
    const size_t SQl = (size_t)DMODEL * DMODEL;
    const int z = blockIdx.z;
    const int which = z >> 2, l = z & 3;
    const float* in = (which == 0 ? wq : which == 1 ? wk : wv) + (size_t)l * SQl;
    __nv_bfloat16* ho = hiT + (size_t)l * 3 * SQl + (size_t)which * SQl;
    __nv_bfloat16* lo = loT + (size_t)l * 3 * SQl + (size_t)which * SQl;
    int k0 = blockIdx.y * 32, n0 = blockIdx.x * 32;
    int tx = threadIdx.x, ty = threadIdx.y;
#pragma unroll
    for (int i = 0; i < 32; i += 8)
        tile[ty + i][tx] = in[(size_t)(k0 + ty + i) * DMODEL + n0 + tx];
    __syncthreads();
#pragma unroll
    for (int i = 0; i < 32; i += 8) {
        ushort h, l2;
        split_bf16(tile[tx][ty + i], h, l2);
        size_t o = (size_t)(n0 + ty + i) * DMODEL + k0 + tx;
        ho[o] = __ushort_as_bfloat16(h); lo[o] = __ushort_as_bfloat16(l2);
    }
}

// ==================================================================================
// 64-wide NT tensor GEMM (block 128x64, 8 warps, warp 32x32)
// 2-stage cp.async double buffer, 3 CTAs/SM. TERMS: 1 = Ahi*Bhi, 2 = +Ahi*Blo,
// 3 = +Alo*Bhi.
// ==================================================================================
#define ASTR 40
#define OFF_AL 5120
#define OFF_BH 10240
#define OFF_BL 12800
#define STG_B  30720
#define DSM_GEMM (2 * STG_B)    // 61440 bytes -> 3 CTAs/SM

template<int TERMS, bool BIAS, bool RES, bool GELU_ACT, bool OUTHL>
__global__ void __launch_bounds__(256, 3)
tmma_nt_kernel(const __nv_bfloat16* __restrict__ Ahi_, const __nv_bfloat16* __restrict__ Alo_,
               const __nv_bfloat16* __restrict__ Bhi_, const __nv_bfloat16* __restrict__ Blo_,
               const float* __restrict__ bias, const float* __restrict__ res,
               float* __restrict__ C,
               __nv_bfloat16* __restrict__ Chi, __nv_bfloat16* __restrict__ Clo,
               int Nout, int K, float alpha) {
    extern __shared__ __align__(16) ushort dsm[];
    const uint32_t base = smem_u32(dsm);

    const int tid = threadIdx.x;
    const int wid = tid >> 5, lane = tid & 31;
    const int bm = blockIdx.y * 128, bn = blockIdx.x * 64;
    const int wm = wid & 3, wn = wid >> 2;
    const int g = lane >> 2, t = lane & 3;
    const int lq = lane >> 3, lr = lane & 7;

    float acc[2][4][4];
#pragma unroll
    for (int i = 0; i < 2; i++)
#pragma unroll
        for (int j = 0; j < 4; j++)
#pragma unroll
            for (int c = 0; c < 4; c++) acc[i][j][c] = 0.f;

    const int arow = tid >> 1, aseg = tid & 1;
    const int brow = tid >> 2, bseg = tid & 3;
    const ushort* gAh = (const ushort*)Ahi_ + (size_t)(bm + arow) * K + aseg * 16;
    const ushort* gAl = (const ushort*)Alo_ + (size_t)(bm + arow) * K + aseg * 16;
    const ushort* gBh = (const ushort*)Bhi_ + (size_t)(bn + brow) * K + bseg * 8;
    const ushort* gBl = (const ushort*)Blo_ + (size_t)(bn + brow) * K + bseg * 8;
    const uint32_t dA = (uint32_t)((arow * ASTR + aseg * 16) * 2);
    const uint32_t dB = (uint32_t)((brow * ASTR + bseg * 8) * 2);

#define TISSUE(sb, kc) do { \
        CP_ASYNC16((sb) + dA, gAh + (kc)); \
        CP_ASYNC16((sb) + dA + 16, gAh + (kc) + 8); \
        if (TERMS == 3) { \
            CP_ASYNC16((sb) + OFF_AL * 2 + dA, gAl + (kc)); \
            CP_ASYNC16((sb) + OFF_AL * 2 + dA + 16, gAl + (kc) + 8); \
        } \
        CP_ASYNC16((sb) + OFF_BH * 2 + dB, gBh + (kc)); \
        if (TERMS >= 2) CP_ASYNC16((sb) + OFF_BL * 2 + dB, gBl + (kc)); \
    } while (0)

    uint32_t aoff[2], boff[2];
#pragma unroll
    for (int mt = 0; mt < 2; mt++) {
        int row = wm * 32 + mt * 16 + (lq & 1) * 8 + lr;
        int col = (lq >> 1) * 8;
        aoff[mt] = (uint32_t)((row * ASTR + col) * 2);
    }
#pragma unroll
    for (int p = 0; p < 2; p++) {
        int row = wn * 32 + p * 16 + (lq >> 1) * 8 + lr;
        int col = (lq & 1) * 8;
        boff[p] = (uint32_t)((row * ASTR + col) * 2);
    }

    const int nch = K >> 5;
    TISSUE(base, 0);
    CP_COMMIT();

    for (int ch = 0; ch < nch; ch++) {
        if (ch + 1 < nch) {
            TISSUE(base + ((ch + 1) & 1) * STG_B, (ch + 1) * 32);
        }
        CP_COMMIT();
        CP_WAIT1();
        __syncthreads();

        const uint32_t sb = base + (ch & 1) * STG_B;
#pragma unroll
        for (int kk = 0; kk < 32; kk += 16) {
            const uint32_t kb = (uint32_t)(kk * 2);
            uint32_t rah[2][4], ral[2][4], rbh[2][4], rbl[2][4];
#pragma unroll
            for (int mt = 0; mt < 2; mt++) {
                LDSM4(rah[mt][0], rah[mt][1], rah[mt][2], rah[mt][3], sb + aoff[mt] + kb);
                if (TERMS == 3)
                    LDSM4(ral[mt][0], ral[mt][1], ral[mt][2], ral[mt][3],
                          sb + OFF_AL * 2 + aoff[mt] + kb);
            }
#pragma unroll
            for (int p = 0; p < 2; p++) {
                LDSM4(rbh[p][0], rbh[p][1], rbh[p][2], rbh[p][3],
                      sb + OFF_BH * 2 + boff[p] + kb);
                if (TERMS >= 2)
                    LDSM4(rbl[p][0], rbl[p][1], rbl[p][2], rbl[p][3],
                          sb + OFF_BL * 2 + boff[p] + kb);
            }
#pragma unroll
            for (int mt = 0; mt < 2; mt++)
#pragma unroll
                for (int p = 0; p < 2; p++)
#pragma unroll
                    for (int sub = 0; sub < 2; sub++) {
                        const int nt = 2 * p + sub;
                        MMA16816(acc[mt][nt], rah[mt], &rbh[p][2 * sub]);
                        if (TERMS >= 2) MMA16816(acc[mt][nt], rah[mt], &rbl[p][2 * sub]);
                        if (TERMS == 3) MMA16816(acc[mt][nt], ral[mt], &rbh[p][2 * sub]);
                    }
        }
        __syncthreads();
    }
#undef TISSUE

#pragma unroll
    for (int mt = 0; mt < 2; mt++) {
        int row0 = bm + wm * 32 + mt * 16 + g;
#pragma unroll
        for (int nt = 0; nt < 4; nt++) {
            int col = bn + wn * 32 + nt * 8 + t * 2;
#pragma unroll
            for (int h = 0; h < 2; h++) {
                int r = row0 + h * 8;
                float v0 = acc[mt][nt][h * 2 + 0] * alpha;
                float v1 = acc[mt][nt][h * 2 + 1] * alpha;
                if (BIAS) {
                    const float2 bv = *(const float2*)(bias + col);
                    v0 += bv.x; v1 += bv.y;
                }
                if (RES) {
                    const float2 rr = *(const float2*)(res + (size_t)r * Nout + col);
                    v0 += rr.x; v1 += rr.y;
                }
                if (GELU_ACT) { v0 = gelu_f(v0); v1 = gelu_f(v1); }
                if (OUTHL) {
                    ushort h0, l0, h1, l1;
                    split_bf16(v0, h0, l0);
                    split_bf16(v1, h1, l1);
                    *(uint32_t*)((ushort*)Chi + (size_t)r * Nout + col) =
                        ((uint32_t)h1 << 16) | h0;
                    *(uint32_t*)((ushort*)Clo + (size_t)r * Nout + col) =
                        ((uint32_t)l1 << 16) | l0;
                } else {
                    *(float2*)(C + (size_t)r * Nout + col) = make_float2(v0, v1);
                }
            }
        }
    }
}

// ---------------- embedding (+ hi/lo) ----------------
__global__ void embed_conv_kernel(const int* __restrict__ ids,
                                  const float* __restrict__ tok,
                                  const float* __restrict__ pos,
                                  float* __restrict__ x,
                                  __nv_bfloat16* __restrict__ hi,
                                  __nv_bfloat16* __restrict__ lo) {
    int t = blockIdx.x;
    int s = t & (TSEQ - 1);
    int id = ids[t];
    const float* tp = tok + (size_t)id * DMODEL;
    const float* pp = pos + (size_t)s * DMODEL;
    size_t o = (size_t)t * DMODEL;
    for (int d = threadIdx.x; d < DMODEL; d += 256) {
        float v = tp[d] + pp[d];
        x[o + d] = v;
        ushort h, l;
        split_bf16(v, h, l);
        hi[o + d] = __ushort_as_bfloat16(h);
        lo[o + d] = __ushort_as_bfloat16(l);
    }
}

// ---------------- RMS norm (+ hi/lo) ----------------
__global__ void rms_conv_kernel(float* __restrict__ x, const float* __restrict__ w,
                                __nv_bfloat16* __restrict__ hi,
                                __nv_bfloat16* __restrict__ lo) {
    __shared__ float sred[256];
    int t = blockIdx.x;
    int tid = threadIdx.x;
    float* row = x + (size_t)t * DMODEL;
    float v0 = row[tid];
    float v1 = row[tid + 256];
    sred[tid] = v0 * v0 + v1 * v1;
    __syncthreads();
    for (int s = 128; s > 0; s >>= 1) {
        if (tid < s) sred[tid] += sred[tid + s];
        __syncthreads();
    }
    float r = rsqrtf(sred[0] / (float)DMODEL + 1e-8f);
    float o0 = v0 * r * w[tid];
    float o1 = v1 * r * w[tid + 256];
    row[tid] = o0; row[tid + 256] = o1;
    size_t o = (size_t)t * DMODEL;
    ushort h, l;
    split_bf16(o0, h, l);
    hi[o + tid] = __ushort_as_bfloat16(h); lo[o + tid] = __ushort_as_bfloat16(l);
    split_bf16(o1, h, l);
    hi[o + tid + 256] = __ushort_as_bfloat16(h); lo[o + tid + 256] = __ushort_as_bfloat16(l);
}

// ---------------- K transpose ----------------
__global__ void transpose_k_kernel(const float* __restrict__ QKV, float* __restrict__ KT) {
    __shared__ float tile[32][33];
    int b = blockIdx.z;
    int t0 = blockIdx.y * 32;
    int c0 = blockIdx.x * 32;
    int tx = threadIdx.x, ty = threadIdx.y;
#pragma unroll
    for (int i = 0; i < 32; i += 8)
        tile[ty + i][tx] = QKV[(size_t)(b * TSEQ + t0 + ty + i) * (3 * DMODEL) + DMODEL + c0 + tx];
    __syncthreads();
#pragma unroll
    for (int i = 0; i < 32; i += 8)
        KT[(size_t)(b * DMODEL + c0 + ty + i) * TSEQ + t0 + tx] = tile[tx][ty + i];
}

// ---------------- attention ----------------
#define ATT_Q 16
#define ATT_T 512
#define ATT_SMEM ((ATT_Q * TSEQ + DHEAD * ATT_Q + 8 * ATT_Q * DHEAD + ATT_Q) * 4)

__global__ void attn_kernel(const float* __restrict__ QKV, const float* __restrict__ KT,
                            __nv_bfloat16* __restrict__ Ohi, __nv_bfloat16* __restrict__ Olo) {
    extern __shared__ float smem[];
    float* sS    = smem;
    float* sQT   = sS + ATT_Q * TSEQ;
    float* sPart = sQT + DHEAD * ATT_Q;
    float* sL    = sPart + 8 * ATT_Q * DHEAD;
    const int b = blockIdx.z, h = blockIdx.y;
    const int q0 = blockIdx.x * ATT_Q;
    const int tid = threadIdx.x;

    for (int i = tid; i < ATT_Q * DHEAD; i += ATT_T) {
        int qi = i >> 6, d = i & 63;
        sQT[d * ATT_Q + qi] =
            QKV[(size_t)(b * TSEQ + q0 + qi) * (3 * DMODEL) + h * DHEAD + d];
    }
    __syncthreads();

    {
        const float* kbase = KT + ((size_t)(b * DMODEL) + h * DHEAD) * TSEQ;
        for (int k = tid; k < TSEQ; k += ATT_T) {
            float a[ATT_Q];
#pragma unroll
            for (int qi = 0; qi < ATT_Q; qi++) a[qi] = 0.f;
#pragma unroll 8
            for (int d = 0; d < DHEAD; d++) {
                float kv = kbase[(size_t)d * TSEQ + k];
                const float4* qp = (const float4*)(sQT + d * ATT_Q);
                float4 q0v = qp[0], q1v = qp[1], q2v = qp[2], q3v = qp[3];
                a[0]  += kv * q0v.x; a[1]  += kv * q0v.y; a[2]  += kv * q0v.z; a[3]  += kv * q0v.w;
                a[4]  += kv * q1v.x; a[5]  += kv * q1v.y; a[6]  += kv * q1v.z; a[7]  += kv * q1v.w;
                a[8]  += kv * q2v.x; a[9]  += kv * q2v.y; a[10] += kv * q2v.z; a[11] += kv * q2v.w;
                a[12] += kv * q3v.x; a[13] += kv * q3v.y; a[14] += kv * q3v.z; a[15] += kv * q3v.w;
            }
#pragma unroll
            for (int qi = 0; qi < ATT_Q; qi++) sS[qi * TSEQ + k] = a[qi] * 0.125f;
        }
    }
    __syncthreads();

    {
        const int w = tid >> 5, lane = tid & 31;
        float* row = sS + w * TSEQ;
        float m = -INFINITY;
        for (int k = lane; k < TSEQ; k += 32) m = fmaxf(m, row[k]);
#pragma unroll
        for (int o = 16; o > 0; o >>= 1) m = fmaxf(m, __shfl_xor_sync(0xFFFFFFFF, m, o));
        float sum = 0.f;
        for (int k = lane; k < TSEQ; k += 32) {
            float e = expf(row[k] - m);
            row[k] = e;
            sum += e;
        }
#pragma unroll
        for (int o = 16; o > 0; o >>= 1) sum += __shfl_xor_sync(0xFFFFFFFF, sum, o);
        if (lane == 0) sL[w] = sum;
    }
    __syncthreads();

    {
        int d = tid & 63, chunk = tid >> 6;
        const float* vbase = QKV + (size_t)(b * TSEQ) * (3 * DMODEL) + 2 * DMODEL + h * DHEAD + d;
        float a[ATT_Q];
#pragma unroll
        for (int qi = 0; qi < ATT_Q; qi++) a[qi] = 0.f;
        int k0 = chunk * (TSEQ / 8);
        for (int k = k0; k < k0 + TSEQ / 8; k++) {
            float vv = vbase[(size_t)k * (3 * DMODEL)];
#pragma unroll
            for (int qi = 0; qi < ATT_Q; qi++) a[qi] += sS[qi * TSEQ + k] * vv;
        }
#pragma unroll
        for (int qi = 0; qi < ATT_Q; qi++)
            sPart[(chunk * ATT_Q + qi) * DHEAD + d] = a[qi];
    }
    __syncthreads();
    for (int i = tid; i < ATT_Q * DHEAD; i += ATT_T) {
        int qi = i >> 6, d = i & 63;
        float s = 0.f;
#pragma unroll
        for (int c = 0; c < 8; c++) s += sPart[(c * ATT_Q + qi) * DHEAD + d];
        float o = s / sL[qi];
        ushort hh, ll;
        split_bf16(o, hh, ll);
        size_t oo = (size_t)(b * TSEQ + q0 + qi) * DMODEL + h * DHEAD + d;
        Ohi[oo] = __ushort_as_bfloat16(hh);
        Olo[oo] = __ushort_as_bfloat16(ll);
    }
}

// ---------------- top-8 select (approx) + exact rescore + softmax + gather --------
// Identical structure to the proven KTOP=8 kernel; only addition is an exact
// fp32 rescore of the 8 selected slots (q reconstructed from hi+lo).
__global__ void topk_read_kernel(const float* __restrict__ scores,
                                 const float* __restrict__ memV,
                                 const __nv_bfloat16* __restrict__ qhi,
                                 const __nv_bfloat16* __restrict__ qlo,
                                 const float* __restrict__ memK,
                                 const float* __restrict__ sal,
                                 __nv_bfloat16* __restrict__ rdhi,
                                 __nv_bfloat16* __restrict__ rdlo) {
    __shared__ float ssc[256][KTOP];
    __shared__ int   sid[256][KTOP];
    __shared__ int   scand[KTOP];
    __shared__ float sexact[KTOP];
    __shared__ float sw[KTOP];
    __shared__ int   swi[KTOP];
    const int t = blockIdx.x;
    const int tid = threadIdx.x;
    const float* row = scores + (size_t)t * NSLOTS;

    float ls[KTOP]; int li[KTOP];
#pragma unroll
    for (int j = 0; j < KTOP; j++) { ls[j] = -INFINITY; li[j] = -1; }
    for (int s = tid; s < NSLOTS; s += 256) {
        float v = row[s];
        if (v > ls[KTOP - 1]) {
            int j = KTOP - 1;
            while (j > 0 && ls[j - 1] < v) { ls[j] = ls[j - 1]; li[j] = li[j - 1]; j--; }
            ls[j] = v; li[j] = s;
        }
    }
#pragma unroll
    for (int j = 0; j < KTOP; j++) { ssc[tid][j] = ls[j]; sid[tid][j] = li[j]; }

    for (int stride = 128; stride >= 1; stride >>= 1) {
        __syncthreads();
        if (tid < stride) {
            float oa[KTOP]; int oi[KTOP];
            int ai = 0, bi = 0;
#pragma unroll
            for (int j = 0; j < KTOP; j++) {
                float av = ssc[tid][ai], bv = ssc[tid + stride][bi];
                if (av >= bv) { oa[j] = av; oi[j] = sid[tid][ai]; ai++; }
                else          { oa[j] = bv; oi[j] = sid[tid + stride][bi]; bi++; }
            }
#pragma unroll
            for (int j = 0; j < KTOP; j++) { ssc[tid][j] = oa[j]; sid[tid][j] = oi[j]; }
        }
    }
    __syncthreads();
    if (tid < KTOP) scand[tid] = sid[0][tid];
    __syncthreads();

    // exact rescore of the 8 selected slots: warp w handles slot w
    {
        const int w = tid >> 5, lane = tid & 31;  // 8 warps == KTOP
        const int slot = scand[w];
        const ushort* qh = (const ushort*)qhi + (size_t)t * DMODEL;
        const ushort* ql = (const ushort*)qlo + (size_t)t * DMODEL;
        const float* kr = memK + (size_t)slot * DMODEL;
        float s = 0.f;
        for (int i = lane; i < DMODEL; i += 32) {
            float qv = __bfloat162float(__ushort_as_bfloat16(qh[i]))
                     + __bfloat162float(__ushort_as_bfloat16(ql[i]));
            s += qv * kr[i];
        }
#pragma unroll
        for (int o = 16; o > 0; o >>= 1) s += __shfl_xor_sync(0xFFFFFFFF, s, o);
        if (lane == 0)
            sexact[w] = s * 0.044194173824159216f + sal[slot];
    }
    __syncthreads();

    // softmax over the 8 exact scores (order-invariant, no sort needed)
    if (tid == 0) {
        float m = -INFINITY;
#pragma unroll
        for (int j = 0; j < KTOP; j++) m = fmaxf(m, sexact[j]);
        float e[KTOP]; float sum = 0.f;
#pragma unroll
        for (int j = 0; j < KTOP; j++) { e[j] = expf(sexact[j] - m); sum += e[j]; }
        float inv = 1.f / sum;
#pragma unroll
        for (int j = 0; j < KTOP; j++) { sw[j] = e[j] * inv; swi[j] = scand[j]; }
    }
    __syncthreads();

    for (int d = tid; d < DMODEL; d += 256) {
        float acc = 0.f;
#pragma unroll
        for (int j = 0; j < KTOP; j++)
            acc += sw[j] * memV[(size_t)swi[j] * DMODEL + d];
        ushort h, l;
        split_bf16(acc, h, l);
        size_t o = (size_t)t * DMODEL + d;
        rdhi[o] = __ushort_as_bfloat16(h);
        rdlo[o] = __ushort_as_bfloat16(l);
    }
}

// ---------------- host orchestration ----------------
extern "C" void kernel_launch(void* const* d_in, const int* in_sizes, int n_in,
                              void* d_out, int out_size) {
    const int*   ids      = (const int*)  d_in[0];
    const float* tok      = (const float*)d_in[1];
    const float* pos      = (const float*)d_in[2];
    const float* wq       = (const float*)d_in[3];
    const float* wk       = (const float*)d_in[4];
    const float* wv       = (const float*)d_in[5];
    const float* wo       = (const float*)d_in[6];
    const float* bo       = (const float*)d_in[7];
    const float* norm1    = (const float*)d_in[8];
    const float* ffw1     = (const float*)d_in[9];
    const float* ffb1     = (const float*)d_in[10];
    const float* ffw2     = (const float*)d_in[11];
    const float* ffb2     = (const float*)d_in[12];
    const float* norm2    = (const float*)d_in[13];
    const float* memK     = (const float*)d_in[14];
    const float* memV     = (const float*)d_in[15];
    const float* salience = (const float*)d_in[16];
    const float* wq_mem   = (const float*)d_in[17];
    const float* bq_mem   = (const float*)d_in[18];
    const float* w_read   = (const float*)d_in[19];
    const float* b_read   = (const float*)d_in[20];
    const float* norm_out = (const float*)d_in[21];
    float* out = (float*)d_out;

    float *x, *qkv, *kT, *sc;
    cudaGetSymbolAddress((void**)&x,   g_x);
    cudaGetSymbolAddress((void**)&qkv, g_qkv);
    cudaGetSymbolAddress((void**)&kT,  g_kT);
    cudaGetSymbolAddress((void**)&sc,  g_scores);

    __nv_bfloat16 *wThi, *wTlo, *tokhi, *toklo, *mkhi, *mklo, *acthi, *actlo, *ffh, *ffl;
    cudaGetSymbolAddress((void**)&wThi,  g_wT_hi);
    cudaGetSymbolAddress((void**)&wTlo,  g_wT_lo);
    cudaGetSymbolAddress((void**)&tokhi, g_tok_hi);
    cudaGetSymbolAddress((void**)&toklo, g_tok_lo);
    cudaGetSymbolAddress((void**)&mkhi,  g_mk_hi);
    cudaGetSymbolAddress((void**)&mklo,  g_mk_lo);
    cudaGetSymbolAddress((void**)&acthi, g_act_hi);
    cudaGetSymbolAddress((void**)&actlo, g_act_lo);
    cudaGetSymbolAddress((void**)&ffh,   g_ff_hi);
    cudaGetSymbolAddress((void**)&ffl,   g_ff_lo);

    const size_t SQ = (size_t)DMODEL * DMODEL;
    const size_t SF = (size_t)DMODEL * FFDIM;
    const size_t OFF_QKV = 0;
    const size_t OFF_O   = 12 * SQ;
    const size_t OFF_F1  = 16 * SQ;
    const size_t OFF_F2  = OFF_F1 + 4 * SF;
    const size_t OFF_QM  = OFF_F2 + 4 * SF;
    const size_t OFF_RD  = OFF_QM + SQ;

    cudaFuncSetAttribute(tmma_nt_kernel<3, false, false, false, false>, cudaFuncAttributeMaxDynamicSharedMemorySize, DSM_GEMM);
    cudaFuncSetAttribute(tmma_nt_kernel<3, true, true, false, false>,   cudaFuncAttributeMaxDynamicSharedMemorySize, DSM_GEMM);
    cudaFuncSetAttribute(tmma_nt_kernel<3, true, false, true, true>,    cudaFuncAttributeMaxDynamicSharedMemorySize, DSM_GEMM);
    cudaFuncSetAttribute(tmma_nt_kernel<3, true, false, false, true>,   cudaFuncAttributeMaxDynamicSharedMemorySize, DSM_GEMM);
    cudaFuncSetAttribute(tmma_nt_kernel<1, true, false, false, false>,  cudaFuncAttributeMaxDynamicSharedMemorySize, DSM_GEMM);
    cudaFuncSetAttribute(attn_kernel, cudaFuncAttributeMaxDynamicSharedMemorySize, ATT_SMEM);

    const dim3 ct(32, 8);
    const dim3 g512(DMODEL / 64, BT / 128);
    const dim3 gqkv(3 * DMODEL / 64, BT / 128);
    const dim3 g2048(FFDIM / 64, BT / 128);

    // launches ordered so the profiler window hits GEMM / transpose / attn
    conv_T_qkv_kernel<<<dim3(16, 16, 12), ct>>>(wq, wk, wv, wThi + OFF_QKV, wTlo + OFF_QKV);
    conv_T_b_kernel<<<dim3(16, 16, 4), ct>>>(wo, wThi + OFF_O, wTlo + OFF_O, DMODEL, DMODEL, SQ, SQ);
    embed_conv_kernel<<<BT, 256>>>(ids, tok, pos, x, acthi, actlo);
    tmma_nt_kernel<3, false, false, false, false><<<gqkv, 256, DSM_GEMM>>>(
        acthi, actlo, wThi + OFF_QKV, wTlo + OFF_QKV, nullptr, nullptr,
        qkv, nullptr, nullptr, 3 * DMODEL, DMODEL, 1.f);
    transpose_k_kernel<<<dim3(DMODEL / 32, TSEQ / 32, 2), dim3(32, 8)>>>(qkv, kT);
    attn_kernel<<<dim3(TSEQ / ATT_Q, NHEAD, 2), ATT_T, ATT_SMEM>>>(qkv, kT, acthi, actlo);

    // remaining conversions
    conv_T_b_kernel<<<dim3(FFDIM / 32, DMODEL / 32, 4), ct>>>(ffw1, wThi + OFF_F1, wTlo + OFF_F1, DMODEL, FFDIM, SF, SF);
    conv_T_b_kernel<<<dim3(DMODEL / 32, FFDIM / 32, 4), ct>>>(ffw2, wThi + OFF_F2, wTlo + OFF_F2, FFDIM, DMODEL, SF, SF);
    conv_T_b_kernel<<<dim3(16, 16, 1), ct>>>(wq_mem, wThi + OFF_QM, wTlo + OFF_QM, DMODEL, DMODEL, 0, 0);
    conv_T_b_kernel<<<dim3(16, 16, 1), ct>>>(w_read, wThi + OFF_RD, wTlo + OFF_RD, DMODEL, DMODEL, 0, 0);
    conv_rows_kernel<<<(int)((size_t)VSIZE * DMODEL / 1024), 256>>>(tok, tokhi, toklo);
    conv_rows_kernel<<<(int)((size_t)NSLOTS * DMODEL / 1024), 256>>>(memK, mkhi, mklo);

    // layer 0 remainder + layers 1..3
    for (int l = 0; l < 4; l++) {
        if (l > 0) {
            tmma_nt_kernel<3, false, false, false, false><<<gqkv, 256, DSM_GEMM>>>(
                acthi, actlo, wThi + OFF_QKV + l * 3 * SQ, wTlo + OFF_QKV + l * 3 * SQ,
                nullptr, nullptr, qkv, nullptr, nullptr, 3 * DMODEL, DMODEL, 1.f);
            transpose_k_kernel<<<dim3(DMODEL / 32, TSEQ / 32, 2), dim3(32, 8)>>>(qkv, kT);
            attn_kernel<<<dim3(TSEQ / ATT_Q, NHEAD, 2), ATT_T, ATT_SMEM>>>(qkv, kT, acthi, actlo);
        }

        tmma_nt_kernel<3, true, true, false, false><<<g512, 256, DSM_GEMM>>>(
            acthi, actlo, wThi + OFF_O + l * SQ, wTlo + OFF_O + l * SQ,
            bo + l * DMODEL, x, x, nullptr, nullptr, DMODEL, DMODEL, 1.f);
        rms_conv_kernel<<<BT, 256>>>(x, norm1 + l * DMODEL, acthi, actlo);

        tmma_nt_kernel<3, true, false, true, true><<<g2048, 256, DSM_GEMM>>>(
            acthi, actlo, wThi + OFF_F1 + l * SF, wTlo + OFF_F1 + l * SF,
            ffb1 + l * FFDIM, nullptr, nullptr, ffh, ffl, FFDIM, DMODEL, 1.f);
        tmma_nt_kernel<3, true, true, false, false><<<g512, 256, DSM_GEMM>>>(
            ffh, ffl, wThi + OFF_F2 + l * SF, wTlo + OFF_F2 + l * SF,
            ffb2 + l * DMODEL, x, x, nullptr, nullptr, DMODEL, FFDIM, 1.f);
        rms_conv_kernel<<<BT, 256>>>(x, norm2 + l * DMODEL, acthi, actlo);
    }

    // external memory read: q hi/lo (used for approx scores AND exact rescore)
    tmma_nt_kernel<3, true, false, false, true><<<g512, 256, DSM_GEMM>>>(
        acthi, actlo, wThi + OFF_QM, wTlo + OFF_QM,
        bq_mem, nullptr, nullptr, ffh, ffl, DMODEL, DMODEL, 1.f);
    // approx scores: single-term bf16 (selection only; selected slots rescored exactly)
    tmma_nt_kernel<1, true, false, false, false><<<dim3(NSLOTS / 64, BT / 128), 256, DSM_GEMM>>>(
        ffh, ffl, mkhi, mklo, salience, nullptr, sc, nullptr, nullptr,
        NSLOTS, DMODEL, 0.044194173824159216f /* 512^-0.5 */);
    topk_read_kernel<<<BT, 256>>>(sc, memV, ffh, ffl, memK, salience, acthi, actlo);
    tmma_nt_kernel<3, true, true, false, false><<<g512, 256, DSM_GEMM>>>(
        acthi, actlo, wThi + OFF_RD, wTlo + OFF_RD,
        b_read, x, x, nullptr, nullptr, DMODEL, DMODEL, 1.f);
    rms_conv_kernel<<<BT, 256>>>(x, norm_out, acthi, actlo);

    // tied LM head -> d_out
    tmma_nt_kernel<3, false, false, false, false><<<dim3(VSIZE / 64, BT / 128), 256, DSM_GEMM>>>(
        acthi, actlo, tokhi, toklo, nullptr, nullptr, out, nullptr, nullptr,
        VSIZE, DMODEL, 1.f);
}